// round 1
// baseline (speedup 1.0000x reference)
#include <cuda_runtime.h>
#include <cuda_bf16.h>
#include <math.h>

#define B 16
#define NTOT 17064
#define KSEL 1000
#define MAXOUT 100
#define SCORE_THR 0.05f
#define IOU_THR 0.6f

// ---------------- scratch (static device globals; no allocations) ----------------
__device__ unsigned long long g_key[B * NTOT];
__device__ float4             g_box[B * NTOT];
__device__ int                g_cls[B * NTOT];

// ---------------- kernel 1: decode ----------------
__global__ __launch_bounds__(256) void decode_kernel(
    const float* __restrict__ c0, const float* __restrict__ c1,
    const float* __restrict__ c2, const float* __restrict__ c3,
    const float* __restrict__ c4,
    const float* __restrict__ r0, const float* __restrict__ r1,
    const float* __restrict__ r2, const float* __restrict__ r3,
    const float* __restrict__ r4)
{
    int t = blockIdx.x * blockDim.x + threadIdx.x;
    if (t >= B * NTOT) return;
    int b = t / NTOT;
    int a = t - b * NTOT;

    int p, hw, w, stride;
    const float *cp, *rp;
    if (a < 12800)      { p = a;         hw = 12800; w = 128; stride = 8;   cp = c0; rp = r0; }
    else if (a < 16000) { p = a - 12800; hw = 3200;  w = 64;  stride = 16;  cp = c1; rp = r1; }
    else if (a < 16800) { p = a - 16000; hw = 800;   w = 32;  stride = 32;  cp = c2; rp = r2; }
    else if (a < 17008) { p = a - 16800; hw = 208;   w = 16;  stride = 64;  cp = c3; rp = r3; }
    else                { p = a - 17008; hw = 56;    w = 8;   stride = 128; cp = c4; rp = r4; }

    // max + argmax over 80 class logits (track top-2 for sigmoid-tie semantics)
    const float* cb = cp + ((size_t)b * 80) * hw + p;
    float m1 = -INFINITY, m2 = -INFINITY;
    int i1 = 0, i2 = 0;
    #pragma unroll 8
    for (int c = 0; c < 80; c++) {
        float v = cb[(size_t)c * hw];
        if (v > m1) { m2 = m1; i2 = i1; m1 = v; i1 = c; }
        else if (v > m2) { m2 = v; i2 = c; }
    }
    float score = 1.0f / (1.0f + expf(-m1));
    int cls = i1 + 1;
    {   // replicate jnp.argmax-over-sigmoid first-occurrence ties
        float s2 = 1.0f / (1.0f + expf(-m2));
        if (s2 == score && i2 < i1) cls = i2 + 1;
    }

    // decode box
    float px = (float)(p % w), py = (float)(p / w);
    float ccx = px * (float)stride + 0.5f * (float)stride;
    float ccy = py * (float)stride + 0.5f * (float)stride;
    const float* rb = rp + ((size_t)b * 4) * hw + p;
    float rr0 = rb[0];
    float rr1 = rb[(size_t)hw];
    float rr2 = rb[(size_t)2 * hw];
    float rr3 = rb[(size_t)3 * hw];
    float4 box;
    box.x = ccx - rr0; box.y = ccy - rr1;
    box.z = ccx + rr2; box.w = ccy + rr3;

    size_t o = (size_t)b * NTOT + a;
    g_box[o] = box;
    g_cls[o] = cls;

    // key: descending score, ties -> lower index first (matches lax.top_k)
    unsigned u = __float_as_uint(score);
    u = (u & 0x80000000u) ? ~u : (u | 0x80000000u);
    g_key[o] = ((unsigned long long)u << 32) |
               (unsigned long long)(0xFFFFFFFFu - (unsigned)a);
}

// ---------------- kernel 2: per-batch radix-select + sort + DIoU-NMS + output ----------------
__global__ __launch_bounds__(1024, 1) void select_nms_kernel(float* __restrict__ out)
{
    const int b   = blockIdx.x;
    const int tid = threadIdx.x;
    const unsigned long long* keys = g_key + (size_t)b * NTOT;

    __shared__ unsigned int hist[256];
    __shared__ unsigned long long s_prefix;
    __shared__ int s_k;
    __shared__ int s_cnt;
    __shared__ float s_maxc;
    __shared__ float warpred[32];
    __shared__ unsigned long long sk[1024];
    __shared__ float sx1[1024], sy1[1024], sx2[1024], sy2[1024];
    __shared__ float sar[1024], scx[1024], scy[1024];
    __shared__ int skeep[1024];
    __shared__ int sscan[1024];

    // ---- 8-pass radix select: find the KSEL-th largest 64-bit key exactly ----
    unsigned long long prefix = 0;
    int K = KSEL;
    for (int pass = 0; pass < 8; ++pass) {
        if (tid < 256) hist[tid] = 0;
        __syncthreads();
        int shift = 56 - 8 * pass;
        for (int i = tid; i < NTOT; i += 1024) {
            unsigned long long k = keys[i];
            bool match = (pass == 0) || ((k >> (shift + 8)) == prefix);
            if (match) atomicAdd(&hist[(unsigned)((k >> shift) & 255ULL)], 1u);
        }
        __syncthreads();
        if (tid == 0) {
            unsigned cum = 0; int d = 255;
            for (; d >= 0; --d) { cum += hist[d]; if ((int)cum >= K) break; }
            s_k = K - (int)(cum - hist[d]);
            s_prefix = (prefix << 8) | (unsigned long long)(unsigned)d;
        }
        __syncthreads();
        prefix = s_prefix;
        K = s_k;
        __syncthreads();
    }
    const unsigned long long T = prefix;   // exact 1000th-largest key (keys unique)

    // ---- compact keys >= T into shared (exactly KSEL of them) ----
    if (tid == 0) s_cnt = 0;
    __syncthreads();
    for (int i = tid; i < NTOT; i += 1024) {
        unsigned long long k = keys[i];
        if (k >= T) { int pp = atomicAdd(&s_cnt, 1); sk[pp] = k; }
    }
    __syncthreads();
    if (tid >= s_cnt) sk[tid] = 0ULL;
    __syncthreads();

    // ---- bitonic sort ascending, 1024 keys ----
    for (int kk = 2; kk <= 1024; kk <<= 1) {
        for (int j = kk >> 1; j > 0; j >>= 1) {
            int ixj = tid ^ j;
            if (ixj > tid) {
                unsigned long long av = sk[tid], bv = sk[ixj];
                bool asc = ((tid & kk) == 0);
                if ((av > bv) == asc) { sk[tid] = bv; sk[ixj] = av; }
            }
            __syncthreads();
        }
    }

    // ---- gather rank-tid detection ----
    bool have = (tid < KSEL);
    float score = -2.0f; int mycls = 0; float4 mybox = make_float4(0,0,0,0);
    if (have) {
        unsigned long long mk = sk[1023 - tid];          // tid-th largest
        unsigned idx = 0xFFFFFFFFu - (unsigned)(mk & 0xFFFFFFFFull);
        unsigned su  = (unsigned)(mk >> 32);
        su = (su & 0x80000000u) ? (su & 0x7FFFFFFFu) : ~su;
        score = __uint_as_float(su);
        mycls = g_cls[(size_t)b * NTOT + idx];
        mybox = g_box[(size_t)b * NTOT + idx];
    }
    bool valid = have && (score >= SCORE_THR);

    // ---- max coordinate over valid boxes ----
    float mc = valid ? fmaxf(fmaxf(mybox.x, mybox.y), fmaxf(mybox.z, mybox.w)) : -INFINITY;
    for (int o = 16; o; o >>= 1) mc = fmaxf(mc, __shfl_xor_sync(0xffffffffu, mc, o));
    if ((tid & 31) == 0) warpred[tid >> 5] = mc;
    __syncthreads();
    if (tid < 32) {
        float v = warpred[tid];
        for (int o = 16; o; o >>= 1) v = fmaxf(v, __shfl_xor_sync(0xffffffffu, v, o));
        if (tid == 0) s_maxc = v;
    }
    __syncthreads();
    float maxc = s_maxc;

    // ---- class-offset shift (applied BEFORE area/center, like the reference) ----
    float off = (float)mycls * (maxc + 1.0f);
    float x1 = mybox.x + off, y1 = mybox.y + off;
    float x2 = mybox.z + off, y2 = mybox.w + off;
    float area = (x2 - x1 + 1.0f) * (y2 - y1 + 1.0f);
    float cx = (x1 + x2) * 0.5f, cy = (y1 + y2) * 0.5f;
    sx1[tid] = x1; sy1[tid] = y1; sx2[tid] = x2; sy2[tid] = y2;
    sar[tid] = area; scx[tid] = cx; scy[tid] = cy;
    skeep[tid] = valid ? 1 : 0;
    __syncthreads();

    // ---- serial greedy DIoU-NMS ----
    int keepj = skeep[tid];
    for (int i = 0; i < KSEL; i++) {
        if (skeep[i] && keepj && tid > i) {
            float xmin = fmaxf(sx1[i], x1);
            float ymin = fmaxf(sy1[i], y1);
            float xmax = fminf(sx2[i], x2);
            float ymax = fminf(sy2[i], y2);
            float inter = fmaxf(xmax - xmin, 0.0f) * fmaxf(ymax - ymin, 0.0f);
            float denom = sar[i] + area - inter;
            if (inter > IOU_THR * denom) {     // conservative: diou <= iou
                float iou = inter / denom;
                float dx = scx[i] - cx, dy = scy[i] - cy;
                float idg = dx * dx + dy * dy;
                float ox = fmaxf(sx2[i], x2) - fminf(sx1[i], x1);
                float oy = fmaxf(sy2[i], y2) - fminf(sy1[i], y1);
                float odg = ox * ox + oy * oy;
                float diou = iou - idg / fmaxf(odg, 1e-12f);
                if (diou > IOU_THR) { keepj = 0; skeep[tid] = 0; }
            }
        }
        __syncthreads();
    }

    // ---- rank via inclusive scan ----
    sscan[tid] = keepj;
    __syncthreads();
    for (int d = 1; d < 1024; d <<= 1) {
        int v = sscan[tid];
        int add = (tid >= d) ? sscan[tid - d] : 0;
        __syncthreads();
        sscan[tid] = v + add;
        __syncthreads();
    }
    int rank = sscan[tid] - 1;

    // ---- output: scores [B,100] || classes [B,100] || boxes [B,100,4], all f32 ----
    float* oS = out + (size_t)b * MAXOUT;
    float* oC = out + (size_t)B * MAXOUT + (size_t)b * MAXOUT;
    float* oB = out + (size_t)2 * B * MAXOUT + (size_t)b * MAXOUT * 4;
    if (tid < MAXOUT) {
        oS[tid] = -2.0f; oC[tid] = -2.0f;
        oB[tid * 4 + 0] = -2.0f; oB[tid * 4 + 1] = -2.0f;
        oB[tid * 4 + 2] = -2.0f; oB[tid * 4 + 3] = -2.0f;
    }
    __syncthreads();
    if (keepj && rank < MAXOUT) {
        oS[rank] = score;
        oC[rank] = (float)mycls;
        oB[rank * 4 + 0] = mybox.x; oB[rank * 4 + 1] = mybox.y;
        oB[rank * 4 + 2] = mybox.z; oB[rank * 4 + 3] = mybox.w;
    }
}

// ---------------- launch ----------------
extern "C" void kernel_launch(void* const* d_in, const int* in_sizes, int n_in,
                              void* d_out, int out_size)
{
    const float* cls[5] = {0,0,0,0,0};
    const float* reg[5] = {0,0,0,0,0};
    for (int i = 0; i < n_in; i++) {
        switch (in_sizes[i]) {
            case 16384000: cls[0] = (const float*)d_in[i]; break;
            case  4096000: cls[1] = (const float*)d_in[i]; break;
            case  1024000: cls[2] = (const float*)d_in[i]; break;
            case   266240: cls[3] = (const float*)d_in[i]; break;
            case    71680: cls[4] = (const float*)d_in[i]; break;
            case   819200: reg[0] = (const float*)d_in[i]; break;
            case   204800: reg[1] = (const float*)d_in[i]; break;
            case    51200: reg[2] = (const float*)d_in[i]; break;
            case    13312: reg[3] = (const float*)d_in[i]; break;
            case     3584: reg[4] = (const float*)d_in[i]; break;
            default: break; // anchors (unused): 6400 / 1600 / 1600
        }
    }
    int total = B * NTOT;
    decode_kernel<<<(total + 255) / 256, 256>>>(
        cls[0], cls[1], cls[2], cls[3], cls[4],
        reg[0], reg[1], reg[2], reg[3], reg[4]);
    select_nms_kernel<<<B, 1024>>>((float*)d_out);
}

// round 2
// speedup vs baseline: 2.1217x; 2.1217x over previous
#include <cuda_runtime.h>
#include <cuda_bf16.h>
#include <math.h>

#define B 16
#define NTOT 17064
#define NPAD 17408          // NTOT padded to multiple of 1024 (uniform warp trips)
#define KSEL 1000
#define MAXOUT 100
#define SCORE_THR 0.05f
#define IOU_THR 0.6f
#define CANDCAP 2048

// ---------------- scratch (static device globals; no allocations) ----------------
__device__ unsigned long long g_key[B * NTOT];
__device__ float4             g_box[B * NTOT];
__device__ int                g_cls[B * NTOT];

// ---------------- kernel 1: decode ----------------
__global__ __launch_bounds__(256) void decode_kernel(
    const float* __restrict__ c0, const float* __restrict__ c1,
    const float* __restrict__ c2, const float* __restrict__ c3,
    const float* __restrict__ c4,
    const float* __restrict__ r0, const float* __restrict__ r1,
    const float* __restrict__ r2, const float* __restrict__ r3,
    const float* __restrict__ r4)
{
    int t = blockIdx.x * blockDim.x + threadIdx.x;
    if (t >= B * NTOT) return;
    int b = t / NTOT;
    int a = t - b * NTOT;

    int p, hw, w, stride;
    const float *cp, *rp;
    if (a < 12800)      { p = a;         hw = 12800; w = 128; stride = 8;   cp = c0; rp = r0; }
    else if (a < 16000) { p = a - 12800; hw = 3200;  w = 64;  stride = 16;  cp = c1; rp = r1; }
    else if (a < 16800) { p = a - 16000; hw = 800;   w = 32;  stride = 32;  cp = c2; rp = r2; }
    else if (a < 17008) { p = a - 16800; hw = 208;   w = 16;  stride = 64;  cp = c3; rp = r3; }
    else                { p = a - 17008; hw = 56;    w = 8;   stride = 128; cp = c4; rp = r4; }

    // max + argmax over 80 class logits (track top-2 for sigmoid-tie semantics)
    const float* cb = cp + ((size_t)b * 80) * hw + p;
    float m1 = -INFINITY, m2 = -INFINITY;
    int i1 = 0, i2 = 0;
    #pragma unroll 8
    for (int c = 0; c < 80; c++) {
        float v = cb[(size_t)c * hw];
        if (v > m1) { m2 = m1; i2 = i1; m1 = v; i1 = c; }
        else if (v > m2) { m2 = v; i2 = c; }
    }
    float score = 1.0f / (1.0f + expf(-m1));
    int cls = i1 + 1;
    {   // replicate jnp.argmax-over-sigmoid first-occurrence ties
        float s2 = 1.0f / (1.0f + expf(-m2));
        if (s2 == score && i2 < i1) cls = i2 + 1;
    }

    // decode box
    float px = (float)(p % w), py = (float)(p / w);
    float ccx = px * (float)stride + 0.5f * (float)stride;
    float ccy = py * (float)stride + 0.5f * (float)stride;
    const float* rb = rp + ((size_t)b * 4) * hw + p;
    float rr0 = rb[0];
    float rr1 = rb[(size_t)hw];
    float rr2 = rb[(size_t)2 * hw];
    float rr3 = rb[(size_t)3 * hw];
    float4 box;
    box.x = ccx - rr0; box.y = ccy - rr1;
    box.z = ccx + rr2; box.w = ccy + rr3;

    size_t o = (size_t)b * NTOT + a;
    g_box[o] = box;
    g_cls[o] = cls;

    // key: descending score, ties -> lower index first (matches lax.top_k)
    unsigned u = __float_as_uint(score);
    u = (u & 0x80000000u) ? ~u : (u | 0x80000000u);
    g_key[o] = ((unsigned long long)u << 32) |
               (unsigned long long)(0xFFFFFFFFu - (unsigned)a);
}

// warp-aggregated histogram add (all 32 lanes must reach this call)
__device__ __forceinline__ void agg_hist(unsigned int* hist, unsigned d, bool match)
{
    unsigned active = __ballot_sync(0xffffffffu, match);
    if (match) {
        unsigned peers = __match_any_sync(active, d);
        int leader = __ffs(peers) - 1;
        if ((int)(threadIdx.x & 31) == leader)
            atomicAdd(&hist[d], (unsigned)__popc(peers));
    }
}

// ---------------- kernel 2: per-batch radix-select + sort + DIoU-NMS + output ----------------
__global__ __launch_bounds__(1024, 1) void select_nms_kernel(float* __restrict__ out)
{
    const int b   = blockIdx.x;
    const int tid = threadIdx.x;
    const unsigned long long* keys = g_key + (size_t)b * NTOT;

    __shared__ unsigned long long sk[1024];           // 8KB  sorted keys
    __shared__ unsigned long long scratch8[CANDCAP];  // 16KB: cand buffer, later x1/y1/x2/y2
    __shared__ float sar[1024], scx[1024], scy[1024]; // 12KB
    __shared__ int   skeep[1024];                     // 4KB
    __shared__ int   sscan[1024];                     // 4KB (aliases hist)
    __shared__ unsigned long long s_prefix;
    __shared__ int s_k, s_cnt, s_cc;
    __shared__ float s_maxc;
    __shared__ float warpred[32];

    unsigned int* hist = (unsigned int*)sscan;                      // 256 bins
    unsigned long long* cand = scratch8;
    float* sx1 = (float*)&scratch8[0];
    float* sy1 = (float*)&scratch8[512];
    float* sx2 = (float*)&scratch8[1024];
    float* sy2 = (float*)&scratch8[1536];

    if (tid == 0) { s_cc = 0; s_cnt = 0; }

    // ---- 8-pass radix select with warp-aggregated atomics + candidate compaction ----
    unsigned long long prefix = 0;
    int K = KSEL;
    bool use_cand = false;
    int ccnt = 0;
    for (int pass = 0; pass < 8; ++pass) {
        if (tid < 256) hist[tid] = 0;
        __syncthreads();
        int shift = 56 - 8 * pass;
        if (!use_cand) {
            for (int i = tid; i < NPAD; i += 1024) {          // uniform trips
                unsigned long long k = (i < NTOT) ? keys[i] : 0ULL;
                bool match = (i < NTOT) &&
                             (pass == 0 || (k >> (shift + 8)) == prefix);
                unsigned d = (unsigned)((k >> shift) & 255ULL);
                agg_hist(hist, d, match);
                if (pass == 2 && match) {
                    int p = atomicAdd(&s_cc, 1);
                    if (p < CANDCAP) cand[p] = k;
                }
            }
        } else {
            for (int i = tid; i < CANDCAP; i += 1024) {        // uniform trips
                unsigned long long k = cand[i];
                bool match = (i < ccnt) && ((k >> (shift + 8)) == prefix);
                unsigned d = (unsigned)((k >> shift) & 255ULL);
                agg_hist(hist, d, match);
            }
        }
        __syncthreads();
        if (tid == 0) {
            unsigned cum = 0; int d = 255;
            for (; d >= 0; --d) { cum += hist[d]; if ((int)cum >= K) break; }
            s_k = K - (int)(cum - hist[d]);
            s_prefix = (prefix << 8) | (unsigned long long)(unsigned)d;
        }
        __syncthreads();
        prefix = s_prefix;
        K = s_k;
        if (pass == 2) { ccnt = s_cc; use_cand = (ccnt <= CANDCAP); }
        __syncthreads();
    }
    const unsigned long long T = prefix;   // exact 1000th-largest key (keys unique)

    // ---- compact keys >= T into sk (exactly KSEL of them) ----
    for (int i = tid; i < NTOT; i += 1024) {
        unsigned long long k = keys[i];
        if (k >= T) { int pp = atomicAdd(&s_cnt, 1); sk[pp] = k; }
    }
    __syncthreads();
    if (tid >= s_cnt) sk[tid] = 0ULL;
    __syncthreads();

    // ---- bitonic sort ascending, 1024 keys ----
    for (int kk = 2; kk <= 1024; kk <<= 1) {
        for (int j = kk >> 1; j > 0; j >>= 1) {
            int ixj = tid ^ j;
            if (ixj > tid) {
                unsigned long long av = sk[tid], bv = sk[ixj];
                bool asc = ((tid & kk) == 0);
                if ((av > bv) == asc) { sk[tid] = bv; sk[ixj] = av; }
            }
            __syncthreads();
        }
    }

    // ---- gather rank-tid detection ----
    bool have = (tid < KSEL);
    float score = -2.0f; int mycls = 0; float4 mybox = make_float4(0,0,0,0);
    if (have) {
        unsigned long long mk = sk[1023 - tid];          // tid-th largest
        unsigned idx = 0xFFFFFFFFu - (unsigned)(mk & 0xFFFFFFFFull);
        unsigned su  = (unsigned)(mk >> 32);
        su = (su & 0x80000000u) ? (su & 0x7FFFFFFFu) : ~su;
        score = __uint_as_float(su);
        mycls = g_cls[(size_t)b * NTOT + idx];
        mybox = g_box[(size_t)b * NTOT + idx];
    }
    bool valid = have && (score >= SCORE_THR);

    // ---- max coordinate over valid boxes ----
    float mc = valid ? fmaxf(fmaxf(mybox.x, mybox.y), fmaxf(mybox.z, mybox.w)) : -INFINITY;
    for (int o = 16; o; o >>= 1) mc = fmaxf(mc, __shfl_xor_sync(0xffffffffu, mc, o));
    if ((tid & 31) == 0) warpred[tid >> 5] = mc;
    __syncthreads();
    if (tid < 32) {
        float v = warpred[tid];
        for (int o = 16; o; o >>= 1) v = fmaxf(v, __shfl_xor_sync(0xffffffffu, v, o));
        if (tid == 0) s_maxc = v;
    }
    __syncthreads();
    float maxc = s_maxc;

    // ---- class-offset shift (applied BEFORE area/center, like the reference) ----
    float off = (float)mycls * (maxc + 1.0f);
    float x1 = mybox.x + off, y1 = mybox.y + off;
    float x2 = mybox.z + off, y2 = mybox.w + off;
    float area = (x2 - x1 + 1.0f) * (y2 - y1 + 1.0f);
    float cx = (x1 + x2) * 0.5f, cy = (y1 + y2) * 0.5f;
    __syncthreads();   // sk reads done; scratch8 (aliased by sx1..sy2) now reusable
    sx1[tid] = x1; sy1[tid] = y1; sx2[tid] = x2; sy2[tid] = y2;
    sar[tid] = area; scx[tid] = cx; scy[tid] = cy;
    skeep[tid] = valid ? 1 : 0;
    __syncthreads();

    // ---- serial greedy DIoU-NMS with early termination at MAXOUT kept ----
    // Row i's keep status is final at iteration i; once MAXOUT rows have
    // survived, all later rows land at rank >= MAXOUT -> scratch slot -> dropped.
    int keepj = skeep[tid];
    int kept_so_far = 0;               // identical across threads (same ki sequence)
    for (int i = 0; i < KSEL; i++) {
        int ki = skeep[i];
        if (ki && keepj && tid > i) {
            float xmin = fmaxf(sx1[i], x1);
            float ymin = fmaxf(sy1[i], y1);
            float xmax = fminf(sx2[i], x2);
            float ymax = fminf(sy2[i], y2);
            float inter = fmaxf(xmax - xmin, 0.0f) * fmaxf(ymax - ymin, 0.0f);
            float denom = sar[i] + area - inter;
            if (inter > IOU_THR * denom) {     // conservative: diou <= iou
                float iou = inter / denom;
                float dx = scx[i] - cx, dy = scy[i] - cy;
                float idg = dx * dx + dy * dy;
                float ox = fmaxf(sx2[i], x2) - fminf(sx1[i], x1);
                float oy = fmaxf(sy2[i], y2) - fminf(sy1[i], y1);
                float odg = ox * ox + oy * oy;
                float diou = iou - idg / fmaxf(odg, 1e-12f);
                if (diou > IOU_THR) { keepj = 0; skeep[tid] = 0; }
            }
        }
        kept_so_far += ki;
        __syncthreads();
        if (kept_so_far >= MAXOUT) break;   // uniform decision
    }

    // ---- rank via inclusive scan ----
    sscan[tid] = keepj;
    __syncthreads();
    for (int d = 1; d < 1024; d <<= 1) {
        int v = sscan[tid];
        int add = (tid >= d) ? sscan[tid - d] : 0;
        __syncthreads();
        sscan[tid] = v + add;
        __syncthreads();
    }
    int rank = sscan[tid] - 1;

    // ---- output: scores [B,100] || classes [B,100] || boxes [B,100,4], all f32 ----
    float* oS = out + (size_t)b * MAXOUT;
    float* oC = out + (size_t)B * MAXOUT + (size_t)b * MAXOUT;
    float* oB = out + (size_t)2 * B * MAXOUT + (size_t)b * MAXOUT * 4;
    if (tid < MAXOUT) {
        oS[tid] = -2.0f; oC[tid] = -2.0f;
        oB[tid * 4 + 0] = -2.0f; oB[tid * 4 + 1] = -2.0f;
        oB[tid * 4 + 2] = -2.0f; oB[tid * 4 + 3] = -2.0f;
    }
    __syncthreads();
    if (keepj && rank < MAXOUT) {
        oS[rank] = score;
        oC[rank] = (float)mycls;
        oB[rank * 4 + 0] = mybox.x; oB[rank * 4 + 1] = mybox.y;
        oB[rank * 4 + 2] = mybox.z; oB[rank * 4 + 3] = mybox.w;
    }
}

// ---------------- launch ----------------
extern "C" void kernel_launch(void* const* d_in, const int* in_sizes, int n_in,
                              void* d_out, int out_size)
{
    const float* cls[5] = {0,0,0,0,0};
    const float* reg[5] = {0,0,0,0,0};
    for (int i = 0; i < n_in; i++) {
        switch (in_sizes[i]) {
            case 16384000: cls[0] = (const float*)d_in[i]; break;
            case  4096000: cls[1] = (const float*)d_in[i]; break;
            case  1024000: cls[2] = (const float*)d_in[i]; break;
            case   266240: cls[3] = (const float*)d_in[i]; break;
            case    71680: cls[4] = (const float*)d_in[i]; break;
            case   819200: reg[0] = (const float*)d_in[i]; break;
            case   204800: reg[1] = (const float*)d_in[i]; break;
            case    51200: reg[2] = (const float*)d_in[i]; break;
            case    13312: reg[3] = (const float*)d_in[i]; break;
            case     3584: reg[4] = (const float*)d_in[i]; break;
            default: break; // anchors (unused)
        }
    }
    int total = B * NTOT;
    decode_kernel<<<(total + 255) / 256, 256>>>(
        cls[0], cls[1], cls[2], cls[3], cls[4],
        reg[0], reg[1], reg[2], reg[3], reg[4]);
    select_nms_kernel<<<B, 1024>>>((float*)d_out);
}